// round 8
// baseline (speedup 1.0000x reference)
#include <cuda_runtime.h>
#include <cstdint>

#define NT     256
#define CAP    3072          // max in-gt anchors per (b,g) row (geom worst ~2100)
#define TOPK   13

#define MAX_N  60
#define MAX_BN 480
#define MAX_BL 172032        // 8 * 21504

// ---------------- device scratch --------------------------------------------
static __device__ float4             g_cand[(size_t)MAX_BN * CAP];  // (met, iou, l, -)
static __device__ int                g_ccnt[MAX_BN];
static __device__ float              g_maxM[MAX_BN], g_maxIou[MAX_BN];
static __device__ int                g_cnt[MAX_BL];
static __device__ unsigned long long g_pk[MAX_BL];

// barrier state
static __device__ unsigned g_bcnt[8];
static __device__ unsigned g_bgen[8];

// ---------------- helpers ---------------------------------------------------
__device__ __forceinline__ void rbox_minmax(float cx, float cy, float w, float h, float r,
                                            float& mnx, float& mxx, float& mny, float& mxy)
{
    float cr = cosf(r), sr = sinf(r);
    float dx = 0.5f * w * cr;
    float dy = 0.5f * h * sr;
    float xr0 = cx + (-dx) * cr - (-dy) * sr;
    float xr1 = cx + ( dx) * cr - (-dy) * sr;
    float xr2 = cx + ( dx) * cr - ( dy) * sr;
    float xr3 = cx + (-dx) * cr - ( dy) * sr;
    float yr0 = cy + (-dx) * sr + (-dy) * cr;
    float yr1 = cy + ( dx) * sr + (-dy) * cr;
    float yr2 = cy + ( dx) * sr + ( dy) * cr;
    float yr3 = cy + (-dx) * sr + ( dy) * cr;
    mnx = fminf(fminf(xr0, xr1), fminf(xr2, xr3));
    mxx = fmaxf(fmaxf(xr0, xr1), fmaxf(xr2, xr3));
    mny = fminf(fminf(yr0, yr1), fminf(yr2, yr3));
    mxy = fmaxf(fmaxf(yr0, yr1), fmaxf(yr2, yr3));
}

__device__ __forceinline__ void grid_bar(int k, unsigned nb)
{
    __syncthreads();
    if (threadIdx.x == 0) {
        __threadfence();
        unsigned gen = *((volatile unsigned*)&g_bgen[k]);
        unsigned old = atomicAdd(&g_bcnt[k], 1u);
        if (old == nb - 1u) {
            g_bcnt[k] = 0u;
            __threadfence();
            atomicAdd(&g_bgen[k], 1u);
        } else {
            while (*((volatile unsigned*)&g_bgen[k]) == gen) { __nanosleep(64); }
        }
        __threadfence();
    }
    __syncthreads();
}

// ---------------- THE fused kernel ------------------------------------------
__global__ void __launch_bounds__(NT, 5)
fused(const float* __restrict__ ps, const float* __restrict__ prb,
      const float* __restrict__ ap, const int* __restrict__ glab,
      const float* __restrict__ gtb, const int* __restrict__ gcrowd,
      const float* __restrict__ pad, const int* __restrict__ bgp,
      float* __restrict__ out, int B, int L, int C, int n, int blocksPerB)
{
    __shared__ float smnx[MAX_N], smxx[MAX_N], smny[MAX_N], smxy[MAX_N], sarea[MAX_N];
    __shared__ float scx[MAX_N], scy[MAX_N], scr[MAX_N], ssr[MAX_N], shw[MAX_N], shh[MAX_N];
    __shared__ int   slab[MAX_N], scrowd[MAX_N];
    __shared__ float sv[CAP];
    __shared__ int   si[CAP];
    __shared__ float s_rv[NT / 32];
    __shared__ int   s_ri[NT / 32], s_rs[NT / 32];
    __shared__ int   s_pos[16], s_zp[16];
    __shared__ int   s_pcnt, s_need, s_npos;

    const int bid  = blockIdx.x;
    const int tid  = threadIdx.x;
    const unsigned nb = gridDim.x;
    const int lane = tid & 31;
    const int wid  = tid >> 5;
    const unsigned lmlt = (1u << lane) - 1u;

    const int b    = bid / blocksPerB;
    const int l    = (bid % blocksPerB) * NT + tid;
    const bool valid = (l < L);
    const int lc   = valid ? l : (L - 1);
    const size_t BL = (size_t)B * L;
    const size_t i  = (size_t)b * L + lc;
    const int row0 = b * n;
    const int BN   = B * n;

    // ---- Phase Z: zero state ----
    for (size_t z = (size_t)bid * NT + tid; z < BL; z += (size_t)nb * NT) {
        g_cnt[z] = 0;
        g_pk[z]  = ~0ULL;
    }
    {
        int z = bid * NT + tid;
        if (z < BN) { g_ccnt[z] = 0; g_maxM[z] = 0.0f; g_maxIou[z] = 0.0f; }
    }
    // GT tables for this block's batch b
    if (tid < n) {
        int gi = row0 + tid;
        float cx = gtb[gi*5+0], cy = gtb[gi*5+1], w = gtb[gi*5+2], h = gtb[gi*5+3], r = gtb[gi*5+4];
        float mnx, mxx, mny, mxy;
        rbox_minmax(cx, cy, w, h, r, mnx, mxx, mny, mxy);
        smnx[tid] = mnx; smxx[tid] = mxx; smny[tid] = mny; smxy[tid] = mxy;
        sarea[tid] = w * h;
        scx[tid] = cx; scy[tid] = cy;
        scr[tid] = cosf(r); ssr[tid] = sinf(r);
        shw[tid] = 0.5f * w; shh[tid] = 0.5f * h;
        slab[tid] = glab[gi];
        scrowd[tid] = gcrowd[gi];
    }

    grid_bar(0, nb);

    // ---- Phase B: candidate sweep (anchor geometry kept in registers) ----
    float cxp = prb[i*5+0], cyp = prb[i*5+1], wp = prb[i*5+2], hp = prb[i*5+3], rp = prb[i*5+4];
    float mnx, mxx, mny, mxy;
    rbox_minmax(cxp, cyp, wp, hp, rp, mnx, mxx, mny, mxy);
    const float area = wp * hp;
    const float ax = ap[2*lc+0], ay = ap[2*lc+1];

    for (int g = 0; g < n; g++) {
        float iw = fminf(mxx, smxx[g]) - fmaxf(mnx, smnx[g]);
        float ih = fminf(mxy, smxy[g]) - fmaxf(mny, smny[g]);
        iw = fmaxf(iw, 0.0f);
        ih = fmaxf(ih, 0.0f);
        float inter = iw * ih;
        float den = area + sarea[g] - inter + 1e-9f;

        float dxp = ax - scx[g];
        float dyp = ay - scy[g];
        float xl =  dxp * scr[g] + dyp * ssr[g];
        float yl = -dxp * ssr[g] + dyp * scr[g];
        bool ing = valid && (fabsf(xl) <= shw[g]) && (fabsf(yl) <= shh[g]);

        unsigned mask = __ballot_sync(0xffffffffu, ing);
        if (mask) {
            int leader = __ffs(mask) - 1;
            int basep = 0;
            if (lane == leader) basep = atomicAdd(&g_ccnt[row0 + g], __popc(mask));
            basep = __shfl_sync(0xffffffffu, basep, leader);
            if (ing) {
                float iou = inter / den;
                iou = fminf(fmaxf(iou, 0.0f), 1.0f);
                float sc = __ldg(&ps[i * C + slab[g]]);
                float i2 = iou * iou;
                float met = sc * (i2 * i2 * i2);
                int p = basep + __popc(mask & lmlt);
                if (p < CAP) {
                    float4 e;
                    e.x = met; e.y = iou; e.z = __int_as_float(l); e.w = 0.0f;
                    g_cand[(size_t)(row0 + g) * CAP + p] = e;
                }
            }
        }
    }

    grid_bar(1, nb);

    // ---- Phase C: block-per-row exact top-13 ----
    if (bid < BN) {
        int row = bid;
        int bC = row / n;
        int gC = row - bC * n;
        bool padf = (pad[row] != 0.0f);
        int cnt = g_ccnt[row];
        if (cnt > CAP) cnt = CAP;
        size_t cbase = (size_t)row * CAP;
        size_t abase = (size_t)bC * L;
        unsigned long long gkey = (unsigned long long)gC << 32;

        int np = 0;
        for (int j = tid; j < cnt; j += NT) {
            float4 e = g_cand[cbase + j];
            sv[j] = e.x;
            si[j] = __float_as_int(e.z);
            if (e.x > 0.0f) np++;
        }
        #pragma unroll
        for (int o = 16; o > 0; o >>= 1) np += __shfl_xor_sync(0xffffffffu, np, o);
        if (lane == 0) s_ri[wid] = np;
        __syncthreads();
        if (tid == 0) {
            int t = 0;
            #pragma unroll
            for (int w = 0; w < NT / 32; w++) t += s_ri[w];
            s_npos = t;
        }
        __syncthreads();
        int npos = s_npos;

        if (npos >= TOPK) {
            for (int k = 0; k < TOPK; k++) {
                float bv = -1.0f; int bi = 0x7fffffff; int bs = 0;
                for (int j = tid; j < cnt; j += NT) {
                    float v = sv[j]; int ix = si[j];
                    if (v > bv || (v == bv && ix < bi)) { bv = v; bi = ix; bs = j; }
                }
                #pragma unroll
                for (int o = 16; o > 0; o >>= 1) {
                    float ov = __shfl_xor_sync(0xffffffffu, bv, o);
                    int   oi = __shfl_xor_sync(0xffffffffu, bi, o);
                    int   os = __shfl_xor_sync(0xffffffffu, bs, o);
                    if (ov > bv || (ov == bv && oi < bi)) { bv = ov; bi = oi; bs = os; }
                }
                if (lane == 0) { s_rv[wid] = bv; s_ri[wid] = bi; s_rs[wid] = bs; }
                __syncthreads();
                if (tid == 0) {
                    float fv = s_rv[0]; int fi = s_ri[0], fs = s_rs[0];
                    #pragma unroll
                    for (int w = 1; w < NT / 32; w++) {
                        if (s_rv[w] > fv || (s_rv[w] == fv && s_ri[w] < fi)) {
                            fv = s_rv[w]; fi = s_ri[w]; fs = s_rs[w];
                        }
                    }
                    sv[fs] = -1.0f;
                    if (padf) {
                        atomicAdd(&g_cnt[abase + fi], 1);
                        atomicMin(&g_pk[abase + fi], gkey | (unsigned)fs);
                    }
                }
                __syncthreads();
            }
        } else {
            // all positives are picks; fill with lowest-index zero-valued anchors
            if (tid == 0) s_pcnt = 0;
            __syncthreads();
            for (int j = tid; j < cnt; j += NT) {
                if (sv[j] > 0.0f) {
                    int q = atomicAdd(&s_pcnt, 1);
                    if (q < 16) s_pos[q] = si[j];
                    if (padf) {
                        atomicAdd(&g_cnt[abase + si[j]], 1);
                        atomicMin(&g_pk[abase + si[j]], gkey | (unsigned)j);
                    }
                }
            }
            __syncthreads();
            if (tid == 0) {
                int need = TOPK - npos;
                int nz = 0, idx = 0;
                while (nz < need && idx < L) {
                    bool isp = false;
                    for (int q = 0; q < npos && q < 16; q++)
                        if (s_pos[q] == idx) { isp = true; break; }
                    if (!isp) s_zp[nz++] = idx;
                    idx++;
                }
                s_need = nz;
            }
            __syncthreads();
            int need = s_need;
            for (int j = tid; j < cnt; j += NT) {
                if (!(sv[j] > 0.0f)) {
                    int ix = si[j];
                    for (int q = 0; q < need; q++) {
                        if (s_zp[q] == ix) {
                            if (padf) {
                                atomicAdd(&g_cnt[abase + ix], 1);
                                atomicMin(&g_pk[abase + ix], gkey | (unsigned)j);
                            }
                            break;
                        }
                    }
                }
            }
        }
    }

    grid_bar(2, nb);

    // ---- Phase D: per-anchor assignment (uses GT smem + anchor regs) ----
    int gf = 0; bool pos = false;
    float pm = 0.0f, piou = 0.0f;
    if (valid) {
        int cnt = g_cnt[i];
        if (cnt == 1) {
            unsigned long long pk = g_pk[i];
            gf = (int)(pk >> 32);
            int slot = (int)(pk & 0xffffffffu);
            float4 e = g_cand[(size_t)(row0 + gf) * CAP + slot];
            pm = e.x; piou = e.y;
            pos = true;
        } else if (cnt > 1) {
            float numb = -1.0f, denb = 1.0f;
            for (int g = 0; g < n; g++) {
                float iw = fminf(mxx, smxx[g]) - fmaxf(mnx, smnx[g]);
                float ih = fminf(mxy, smxy[g]) - fmaxf(mny, smny[g]);
                iw = fmaxf(iw, 0.0f);
                ih = fmaxf(ih, 0.0f);
                float inter = iw * ih;
                float den = area + sarea[g] - inter + 1e-9f;
                if (inter * denb > numb * den) { numb = inter; denb = den; gf = g; }
            }
            piou = numb / denb;
            piou = fminf(fmaxf(piou, 0.0f), 1.0f);
            float sc = __ldg(&ps[i * C + slab[gf]]);
            float i2 = piou * piou;
            pm = sc * (i2 * i2 * i2);
            pos = true;
        }

        if (pos) {
            atomicMax((int*)&g_maxM[row0 + gf],   __float_as_int(pm));
            atomicMax((int*)&g_maxIou[row0 + gf], __float_as_int(piou));
        }

        int bg = bgp ? bgp[0] : C;
        out[i] = pos ? (float)slab[gf] : (float)bg;               // labels
        const float* gb = gtb + (size_t)(row0 + gf) * 5;
        #pragma unroll
        for (int j = 0; j < 5; j++) out[BL + i*5 + j] = gb[j];    // rboxes
        out[BL * (size_t)(6 + C) + i] = (float)gf;                // gt index
        out[BL * (size_t)(7 + C) + i] = (float)scrowd[gf];        // crowd
    }

    grid_bar(3, nb);

    // ---- Phase E: assigned_scores ----
    if (valid) {
        float pa = 0.0f;
        int col = -1;
        if (pos) {
            int gi = row0 + gf;
            int lab = slab[gf];
            int bg = bgp ? bgp[0] : C;
            if (scrowd[gf] == 0 && lab != bg) {
                col = (lab > bg) ? (lab - 1) : lab;
                pa = pm / (g_maxM[gi] + 1e-9f) * g_maxIou[gi];
            }
        }
        float* rowp = out + BL * 6 + i * (size_t)C;
        for (int c = 0; c < C; c++) rowp[c] = (c == col) ? pa : 0.0f;
    }
}

// ---------------- launch -----------------------------------------------------
extern "C" void kernel_launch(void* const* d_in, const int* in_sizes, int n_in,
                              void* d_out, int out_size)
{
    const float* pred_scores = (const float*)d_in[0];
    const float* pred_rboxes = (const float*)d_in[1];
    const float* anchor      = (const float*)d_in[2];

    int L = in_sizes[2] / 2;
    int B = in_sizes[1] / (5 * L);
    int C = in_sizes[0] / (B * L);
    int n = in_sizes[3] / B;
    int BN = B * n;

    const int*   glab = (const int*)d_in[3];       // int32 (JAX x64 disabled)
    const float* gtb  = (const float*)d_in[4];

    int idx = 5;
    if (idx < n_in && in_sizes[idx] == 3 * BN) idx++;   // skip gt_poses
    const int*   gcrowd = (const int*)d_in[idx];  idx++;
    const float* pad    = (const float*)d_in[idx]; idx++;
    const int*   bgp    = (idx < n_in && in_sizes[idx] == 1) ? (const int*)d_in[idx] : nullptr;

    int blocksPerB = (L + NT - 1) / NT;
    int grid = B * blocksPerB;

    fused<<<grid, NT>>>(pred_scores, pred_rboxes, anchor, glab, gtb, gcrowd, pad, bgp,
                        (float*)d_out, B, L, C, n, blocksPerB);
}

// round 11
// speedup vs baseline: 1.3010x; 1.3010x over previous
#include <cuda_runtime.h>
#include <cstdint>

#define NT     256
#define NTD    128
#define CAP    3072          // max in-gt anchors per (b,g) row (geom worst ~2100)
#define TOPK   13

#define MAX_N  60
#define MAX_BN 480
#define MAX_BL 172032        // 8 * 21504

// ---------------- device scratch --------------------------------------------
static __device__ float4             g_cand[(size_t)MAX_BN * CAP];  // (met, iou, l, -)
static __device__ int                g_ccnt[MAX_BN];                // zero-init; kC2 resets
static __device__ float              g_maxM[MAX_BN], g_maxIou[MAX_BN];
static __device__ int                g_cnt[MAX_BL];
static __device__ unsigned long long g_pk[MAX_BL];
static __device__ int                g_gfin[MAX_BL];
static __device__ float              g_posM[MAX_BL];

// ---------------- helpers ---------------------------------------------------
// Reference's pseudo-AABB (used for IoU): corners at (±w/2·cos r, ±h/2·sin r), rotated.
__device__ __forceinline__ void rbox_minmax(float cx, float cy, float w, float h, float r,
                                            float& mnx, float& mxx, float& mny, float& mxy)
{
    float cr = cosf(r), sr = sinf(r);
    float dx = 0.5f * w * cr;
    float dy = 0.5f * h * sr;
    float xr0 = cx + (-dx) * cr - (-dy) * sr;
    float xr1 = cx + ( dx) * cr - (-dy) * sr;
    float xr2 = cx + ( dx) * cr - ( dy) * sr;
    float xr3 = cx + (-dx) * cr - ( dy) * sr;
    float yr0 = cy + (-dx) * sr + (-dy) * cr;
    float yr1 = cy + ( dx) * sr + (-dy) * cr;
    float yr2 = cy + ( dx) * sr + ( dy) * cr;
    float yr3 = cy + (-dx) * sr + ( dy) * cr;
    mnx = fminf(fminf(xr0, xr1), fminf(xr2, xr3));
    mxx = fmaxf(fmaxf(xr0, xr1), fmaxf(xr2, xr3));
    mny = fminf(fminf(yr0, yr1), fminf(yr2, yr3));
    mxy = fmaxf(fmaxf(yr0, yr1), fmaxf(yr2, yr3));
}

// ---------------- kernel B: candidate sweep with TRUE-AABB GT culling -------
__global__ void __launch_bounds__(NT)
kB(const float* __restrict__ ps, const float* __restrict__ prb,
   const float* __restrict__ ap, const float* __restrict__ gtb,
   const int* __restrict__ glab, int B, int L, int C, int n)
{
    __shared__ float smnx[MAX_N], smxx[MAX_N], smny[MAX_N], smxy[MAX_N], sarea[MAX_N];
    __shared__ float scx[MAX_N], scy[MAX_N], scr[MAX_N], ssr[MAX_N], shw[MAX_N], shh[MAX_N];
    __shared__ float stx[MAX_N], sty[MAX_N];      // TRUE AABB half-extents (for culling)
    __shared__ int   slab[MAX_N];
    __shared__ int   s_act[MAX_N];
    __shared__ int   s_nact;
    __shared__ float s_wx0[8], s_wx1[8], s_wy0[8], s_wy1[8];
    __shared__ float s_bb[4];

    const int b   = blockIdx.y;
    const int tid = threadIdx.x;
    const int l   = blockIdx.x * NT + tid;
    const int row0 = b * n;
    const int lane = tid & 31;
    const int wid  = tid >> 5;
    const unsigned lmlt = (1u << lane) - 1u;

    const bool valid = (l < L);
    const int lc = valid ? l : (L - 1);
    const size_t i = (size_t)b * L + lc;

    // GT tables from raw gt_bboxes
    if (tid < n) {
        int gi = row0 + tid;
        float cx = gtb[gi*5+0], cy = gtb[gi*5+1], w = gtb[gi*5+2], h = gtb[gi*5+3], r = gtb[gi*5+4];
        float mnx, mxx, mny, mxy;
        rbox_minmax(cx, cy, w, h, r, mnx, mxx, mny, mxy);
        smnx[tid] = mnx; smxx[tid] = mxx; smny[tid] = mny; smxy[tid] = mxy;
        sarea[tid] = w * h;
        scx[tid] = cx; scy[tid] = cy;
        float cr = cosf(r), sr = sinf(r);
        scr[tid] = cr; ssr[tid] = sr;
        float hw = 0.5f * w, hh = 0.5f * h;
        shw[tid] = hw; shh[tid] = hh;
        // true AABB half-extents of the rotated rect (support of point-in-rbox)
        stx[tid] = hw * fabsf(cr) + hh * fabsf(sr);
        sty[tid] = hw * fabsf(sr) + hh * fabsf(cr);
        slab[tid] = glab[gi];
        if (blockIdx.x == 0) { g_maxM[gi] = 0.0f; g_maxIou[gi] = 0.0f; }
    }
    if (tid == 0) s_nact = 0;

    // block anchor-point bbox (warp reduce then cross-warp)
    const float ax = ap[2*lc+0], ay = ap[2*lc+1];
    {
        float x0 = ax, x1 = ax, y0 = ay, y1 = ay;
        #pragma unroll
        for (int o = 16; o > 0; o >>= 1) {
            x0 = fminf(x0, __shfl_xor_sync(0xffffffffu, x0, o));
            x1 = fmaxf(x1, __shfl_xor_sync(0xffffffffu, x1, o));
            y0 = fminf(y0, __shfl_xor_sync(0xffffffffu, y0, o));
            y1 = fmaxf(y1, __shfl_xor_sync(0xffffffffu, y1, o));
        }
        if (lane == 0) { s_wx0[wid] = x0; s_wx1[wid] = x1; s_wy0[wid] = y0; s_wy1[wid] = y1; }
    }
    __syncthreads();
    if (tid == 0) {
        float x0 = s_wx0[0], x1 = s_wx1[0], y0 = s_wy0[0], y1 = s_wy1[0];
        #pragma unroll
        for (int w = 1; w < 8; w++) {
            x0 = fminf(x0, s_wx0[w]); x1 = fmaxf(x1, s_wx1[w]);
            y0 = fminf(y0, s_wy0[w]); y1 = fmaxf(y1, s_wy1[w]);
        }
        s_bb[0] = x0; s_bb[1] = x1; s_bb[2] = y0; s_bb[3] = y1;
    }
    __syncthreads();

    // active-gt compaction: TRUE AABB vs block anchor-point bbox (conservative
    // for the point-in-rotated-rect test)
    if (tid < n) {
        if (scx[tid] + stx[tid] >= s_bb[0] && scx[tid] - stx[tid] <= s_bb[1] &&
            scy[tid] + sty[tid] >= s_bb[2] && scy[tid] - sty[tid] <= s_bb[3]) {
            int q = atomicAdd(&s_nact, 1);
            s_act[q] = tid;
        }
    }
    __syncthreads();
    const int nact = s_nact;

    // anchor pred box
    float cxp = prb[i*5+0], cyp = prb[i*5+1], wp = prb[i*5+2], hp = prb[i*5+3], rp = prb[i*5+4];
    float mnx, mxx, mny, mxy;
    rbox_minmax(cxp, cyp, wp, hp, rp, mnx, mxx, mny, mxy);
    const float area = wp * hp;

    for (int t = 0; t < nact; t++) {
        int g = s_act[t];
        float dxp = ax - scx[g];
        float dyp = ay - scy[g];
        float xl =  dxp * scr[g] + dyp * ssr[g];
        float yl = -dxp * ssr[g] + dyp * scr[g];
        bool ing = valid && (fabsf(xl) <= shw[g]) && (fabsf(yl) <= shh[g]);

        unsigned mask = __ballot_sync(0xffffffffu, ing);
        if (mask) {
            int leader = __ffs(mask) - 1;
            int basep = 0;
            if (lane == leader) basep = atomicAdd(&g_ccnt[row0 + g], __popc(mask));
            basep = __shfl_sync(0xffffffffu, basep, leader);
            if (ing) {
                float iw = fminf(mxx, smxx[g]) - fmaxf(mnx, smnx[g]);
                float ih = fminf(mxy, smxy[g]) - fmaxf(mny, smny[g]);
                iw = fmaxf(iw, 0.0f);
                ih = fmaxf(ih, 0.0f);
                float inter = iw * ih;
                float den = area + sarea[g] - inter + 1e-9f;
                float iou = inter / den;
                iou = fminf(fmaxf(iou, 0.0f), 1.0f);
                float sc = __ldg(&ps[i * C + slab[g]]);
                float i2 = iou * iou;
                float met = sc * (i2 * i2 * i2);
                int p = basep + __popc(mask & lmlt);
                if (p < CAP) {
                    float4 e;
                    e.x = met; e.y = iou; e.z = __int_as_float(l); e.w = 0.0f;
                    g_cand[(size_t)(row0 + g) * CAP + p] = e;
                }
            }
        }
    }
    if (valid) {
        g_cnt[i] = 0;
        g_pk[i]  = ~0ULL;
    }
}

// ---------------- kernel C2: warp-per-row exact top-13 ----------------------
__global__ void kC2(const float* __restrict__ pad, int L, int n)
{
    __shared__ float sv[CAP];
    __shared__ int   si[CAP];
    __shared__ int   s_pos[16];
    __shared__ int   s_zp[16];
    __shared__ int   s_pcnt, s_need;

    int row  = blockIdx.x;                 // b*n + g
    int lane = threadIdx.x;                // 0..31
    int b = row / n;
    int g = row - b * n;
    bool padf = (pad[row] != 0.0f);

    int cnt = g_ccnt[row];
    if (cnt > CAP) cnt = CAP;
    size_t base  = (size_t)row * CAP;
    size_t abase = (size_t)b * L;
    unsigned long long gkey = (unsigned long long)g << 32;

    int npos = 0;
    for (int j = lane; j < cnt; j += 32) {
        float4 e = g_cand[base + j];
        sv[j] = e.x;
        si[j] = __float_as_int(e.z);
        if (e.x > 0.0f) npos++;
    }
    __syncwarp();
    #pragma unroll
    for (int o = 16; o > 0; o >>= 1) npos += __shfl_xor_sync(0xffffffffu, npos, o);

    if (npos >= TOPK) {
        for (int k = 0; k < TOPK; k++) {
            float bv = -1.0f; int bi = 0x7fffffff; int bslot = 0;
            for (int j = lane; j < cnt; j += 32) {
                float v = sv[j]; int ix = si[j];
                if (v > bv || (v == bv && ix < bi)) { bv = v; bi = ix; bslot = j; }
            }
            #pragma unroll
            for (int o = 16; o > 0; o >>= 1) {
                float ov = __shfl_xor_sync(0xffffffffu, bv, o);
                int   oi = __shfl_xor_sync(0xffffffffu, bi, o);
                int   os = __shfl_xor_sync(0xffffffffu, bslot, o);
                if (ov > bv || (ov == bv && oi < bi)) { bv = ov; bi = oi; bslot = os; }
            }
            if (lane == 0) {
                sv[bslot] = -1.0f;   // invalidate pick
                if (padf) {
                    atomicAdd(&g_cnt[abase + bi], 1);
                    atomicMin(&g_pk[abase + bi], gkey | (unsigned)bslot);
                }
            }
            __syncwarp();
        }
    } else {
        // all positives are picks; fill with lowest-index zero-valued anchors.
        if (lane == 0) s_pcnt = 0;
        __syncwarp();
        for (int j = lane; j < cnt; j += 32) {
            if (sv[j] > 0.0f) {
                int q = atomicAdd(&s_pcnt, 1);
                if (q < 16) s_pos[q] = si[j];
                if (padf) {
                    atomicAdd(&g_cnt[abase + si[j]], 1);
                    atomicMin(&g_pk[abase + si[j]], gkey | (unsigned)j);
                }
            }
        }
        __syncwarp();
        if (lane == 0) {
            int need = TOPK - npos;
            int nz = 0, idx = 0;
            while (nz < need && idx < L) {
                bool isp = false;
                for (int q = 0; q < npos && q < 16; q++)
                    if (s_pos[q] == idx) { isp = true; break; }
                if (!isp) s_zp[nz++] = idx;
                idx++;
            }
            s_need = nz;
        }
        __syncwarp();
        int need = s_need;
        // zero-metric candidates (in-gt) that coincide with fill picks count
        for (int j = lane; j < cnt; j += 32) {
            if (!(sv[j] > 0.0f)) {
                int ix = si[j];
                for (int q = 0; q < need; q++) {
                    if (s_zp[q] == ix) {
                        if (padf) {
                            atomicAdd(&g_cnt[abase + ix], 1);
                            atomicMin(&g_pk[abase + ix], gkey | (unsigned)j);
                        }
                        break;
                    }
                }
            }
        }
    }
    __syncwarp();
    if (lane == 0) g_ccnt[row] = 0;   // reset for next call (determinism)
}

// ---------------- kernel D: per-anchor assignment ---------------------------
__global__ void __launch_bounds__(NTD)
kD(const float* __restrict__ ps, const float* __restrict__ prb,
   const float* __restrict__ gtb, const int* __restrict__ glab,
   const int* __restrict__ gcrowd, const int* __restrict__ bgp,
   float* __restrict__ out, int B, int L, int C, int n)
{
    __shared__ float smnx[MAX_N], smxx[MAX_N], smny[MAX_N], smxy[MAX_N], sarea[MAX_N];
    __shared__ int   slab[MAX_N], scrowd[MAX_N];

    int b = blockIdx.y;
    int tid = threadIdx.x;
    int l = blockIdx.x * NTD + tid;
    int row0 = b * n;
    if (tid < n) {
        int gi = row0 + tid;
        float cx = gtb[gi*5+0], cy = gtb[gi*5+1], w = gtb[gi*5+2], h = gtb[gi*5+3], r = gtb[gi*5+4];
        float mnx, mxx, mny, mxy;
        rbox_minmax(cx, cy, w, h, r, mnx, mxx, mny, mxy);
        smnx[tid] = mnx; smxx[tid] = mxx; smny[tid] = mny; smxy[tid] = mxy;
        sarea[tid] = w * h;
        slab[tid] = glab[gi];
        scrowd[tid] = gcrowd[gi];
    }
    __syncthreads();
    if (l >= L) return;

    size_t BL = (size_t)B * L;
    size_t i = (size_t)b * L + l;

    int cnt = g_cnt[i];
    unsigned long long pk = g_pk[i];
    int gf = 0; bool pos = false;
    float pm = 0.0f, piou = 0.0f;

    if (cnt == 1) {
        gf = (int)(pk >> 32);
        int slot = (int)(pk & 0xffffffffu);
        float4 e = g_cand[(size_t)(row0 + gf) * CAP + slot];
        pm = e.x; piou = e.y;
        pos = true;
    } else if (cnt > 1) {
        // argmax-iou over all gts (first-index tie-break), division-free
        float cx = prb[i*5+0], cy = prb[i*5+1], w = prb[i*5+2], h = prb[i*5+3], r = prb[i*5+4];
        float mnx, mxx, mny, mxy;
        rbox_minmax(cx, cy, w, h, r, mnx, mxx, mny, mxy);
        float area = w * h;
        float numb = -1.0f, denb = 1.0f;
        for (int g = 0; g < n; g++) {
            float iw = fminf(mxx, smxx[g]) - fmaxf(mnx, smnx[g]);
            float ih = fminf(mxy, smxy[g]) - fmaxf(mny, smny[g]);
            iw = fmaxf(iw, 0.0f);
            ih = fmaxf(ih, 0.0f);
            float inter = iw * ih;
            float den = area + sarea[g] - inter + 1e-9f;
            if (inter * denb > numb * den) { numb = inter; denb = den; gf = g; }
        }
        piou = numb / denb;
        piou = fminf(fmaxf(piou, 0.0f), 1.0f);
        float sc = __ldg(&ps[i * C + slab[gf]]);
        float i2 = piou * piou;
        pm = sc * (i2 * i2 * i2);
        pos = true;
    }

    g_gfin[i] = pos ? gf : -1;
    g_posM[i] = pm;
    if (pos) {
        atomicMax((int*)&g_maxM[row0 + gf],   __float_as_int(pm));
        atomicMax((int*)&g_maxIou[row0 + gf], __float_as_int(piou));
    }

    int bg = bgp ? bgp[0] : C;
    out[i] = pos ? (float)slab[gf] : (float)bg;               // labels
    const float* gb = gtb + (size_t)(row0 + gf) * 5;
    #pragma unroll
    for (int j = 0; j < 5; j++) out[BL + i*5 + j] = gb[j];    // rboxes
    out[BL * (size_t)(6 + C) + i] = (float)gf;                // gt index
    out[BL * (size_t)(7 + C) + i] = (float)scrowd[gf];        // crowd
}

// ---------------- kernel E2: assigned_scores, thread per (anchor, class) ----
__global__ void kE2(const int* __restrict__ glab, const int* __restrict__ gcrowd,
                    const int* __restrict__ bgp, float* __restrict__ out,
                    int B, int L, int C, int n)
{
    size_t BL = (size_t)B * L;
    size_t t = (size_t)blockIdx.x * blockDim.x + threadIdx.x;
    if (t >= BL * (size_t)C) return;
    size_t i = t / (size_t)C;
    int c = (int)(t - i * (size_t)C);
    int b = (int)(i / L);

    int gf = g_gfin[i];
    float val = 0.0f;
    if (gf >= 0) {
        int gi = b * n + gf;
        int lab = glab[gi];
        int bg = bgp ? bgp[0] : C;
        if (gcrowd[gi] == 0 && lab != bg) {
            int col = (lab > bg) ? (lab - 1) : lab;
            if (col == c) {
                val = g_posM[i] / (g_maxM[gi] + 1e-9f) * g_maxIou[gi];
            }
        }
    }
    out[BL * 6 + t] = val;
}

// ---------------- launch -----------------------------------------------------
extern "C" void kernel_launch(void* const* d_in, const int* in_sizes, int n_in,
                              void* d_out, int out_size)
{
    const float* pred_scores = (const float*)d_in[0];
    const float* pred_rboxes = (const float*)d_in[1];
    const float* anchor      = (const float*)d_in[2];

    int L = in_sizes[2] / 2;
    int B = in_sizes[1] / (5 * L);
    int C = in_sizes[0] / (B * L);
    int n = in_sizes[3] / B;
    int BN = B * n;
    size_t BL = (size_t)B * L;

    const int*   glab = (const int*)d_in[3];       // int32 (JAX x64 disabled)
    const float* gtb  = (const float*)d_in[4];

    int idx = 5;
    if (idx < n_in && in_sizes[idx] == 3 * BN) idx++;   // skip gt_poses
    const int*   gcrowd = (const int*)d_in[idx];  idx++;
    const float* pad    = (const float*)d_in[idx]; idx++;
    const int*   bgp    = (idx < n_in && in_sizes[idx] == 1) ? (const int*)d_in[idx] : nullptr;

    dim3 gB((L + NT - 1) / NT, B);
    kB<<<gB, NT>>>(pred_scores, pred_rboxes, anchor, gtb, glab, B, L, C, n);

    kC2<<<BN, 32>>>(pad, L, n);

    dim3 gD((L + NTD - 1) / NTD, B);
    kD<<<gD, NTD>>>(pred_scores, pred_rboxes, gtb, glab, gcrowd, bgp, (float*)d_out, B, L, C, n);

    size_t totE = BL * (size_t)C;
    kE2<<<(int)((totE + NT - 1) / NT), NT>>>(glab, gcrowd, bgp, (float*)d_out, B, L, C, n);
}

// round 15
// speedup vs baseline: 1.3297x; 1.0221x over previous
#include <cuda_runtime.h>
#include <cstdint>

#define NT     256
#define NTD    128
#define CAP    3072          // max in-gt anchors per (b,g) row (geom worst ~2100)
#define TOPK   13

#define MAX_N  60
#define MAX_BN 480
#define MAX_BL 172032        // 8 * 21504
#define MAX_C  15

// ---------------- device scratch --------------------------------------------
static __device__ float4             g_cand[(size_t)MAX_BN * CAP];  // (met, iou, l, -)
static __device__ int                g_ccnt[MAX_BN];                // zero-init; kC2 resets
static __device__ float              g_maxM[MAX_BN], g_maxIou[MAX_BN];
static __device__ int                g_cnt[MAX_BL];
static __device__ unsigned long long g_pk[MAX_BL];
static __device__ int                g_gfin[MAX_BL];
static __device__ float              g_posM[MAX_BL];

// ---------------- helpers ---------------------------------------------------
// Reference's pseudo-AABB (used for IoU): corners at (±w/2·cos r, ±h/2·sin r), rotated.
__device__ __forceinline__ void rbox_minmax(float cx, float cy, float w, float h, float r,
                                            float& mnx, float& mxx, float& mny, float& mxy)
{
    float cr = cosf(r), sr = sinf(r);
    float dx = 0.5f * w * cr;
    float dy = 0.5f * h * sr;
    float xr0 = cx + (-dx) * cr - (-dy) * sr;
    float xr1 = cx + ( dx) * cr - (-dy) * sr;
    float xr2 = cx + ( dx) * cr - ( dy) * sr;
    float xr3 = cx + (-dx) * cr - ( dy) * sr;
    float yr0 = cy + (-dx) * sr + (-dy) * cr;
    float yr1 = cy + ( dx) * sr + (-dy) * cr;
    float yr2 = cy + ( dx) * sr + ( dy) * cr;
    float yr3 = cy + (-dx) * sr + ( dy) * cr;
    mnx = fminf(fminf(xr0, xr1), fminf(xr2, xr3));
    mxx = fmaxf(fmaxf(xr0, xr1), fmaxf(xr2, xr3));
    mny = fminf(fminf(yr0, yr1), fminf(yr2, yr3));
    mxy = fmaxf(fmaxf(yr0, yr1), fmaxf(yr2, yr3));
}

// ---------------- kernel B: candidate sweep with TRUE-AABB GT culling -------
__global__ void __launch_bounds__(NT)
kB(const float* __restrict__ ps, const float* __restrict__ prb,
   const float* __restrict__ ap, const float* __restrict__ gtb,
   const int* __restrict__ glab, int B, int L, int C, int n)
{
    __shared__ float smnx[MAX_N], smxx[MAX_N], smny[MAX_N], smxy[MAX_N], sarea[MAX_N];
    __shared__ float scx[MAX_N], scy[MAX_N], scr[MAX_N], ssr[MAX_N], shw[MAX_N], shh[MAX_N];
    __shared__ float stx[MAX_N], sty[MAX_N];      // TRUE AABB half-extents (culling)
    __shared__ int   slab[MAX_N];
    __shared__ int   s_act[MAX_N];
    __shared__ int   s_nact;
    __shared__ float s_wx0[8], s_wx1[8], s_wy0[8], s_wy1[8];
    __shared__ float s_bb[4];
    __shared__ float s_prb[NT * 5];

    const int b   = blockIdx.y;
    const int tid = threadIdx.x;
    const int l0  = blockIdx.x * NT;
    const int l   = l0 + tid;
    const int row0 = b * n;
    const int lane = tid & 31;
    const int wid  = tid >> 5;
    const unsigned lmlt = (1u << lane) - 1u;

    const bool valid = (l < L);
    const int lc = valid ? l : (L - 1);
    const size_t i = (size_t)b * L + lc;

    // stage this block's pred rboxes coalesced
    {
        int nElem = min(NT, L - l0) * 5;
        const float* src = prb + ((size_t)b * L + l0) * 5;
        for (int j = tid; j < nElem; j += NT) s_prb[j] = src[j];
    }

    // GT tables from raw gt_bboxes
    if (tid < n) {
        int gi = row0 + tid;
        float cx = gtb[gi*5+0], cy = gtb[gi*5+1], w = gtb[gi*5+2], h = gtb[gi*5+3], r = gtb[gi*5+4];
        float mnx, mxx, mny, mxy;
        rbox_minmax(cx, cy, w, h, r, mnx, mxx, mny, mxy);
        smnx[tid] = mnx; smxx[tid] = mxx; smny[tid] = mny; smxy[tid] = mxy;
        sarea[tid] = w * h;
        scx[tid] = cx; scy[tid] = cy;
        float cr = cosf(r), sr = sinf(r);
        scr[tid] = cr; ssr[tid] = sr;
        float hw = 0.5f * w, hh = 0.5f * h;
        shw[tid] = hw; shh[tid] = hh;
        // true AABB half-extents of the rotated rect (support of point-in-rbox)
        stx[tid] = hw * fabsf(cr) + hh * fabsf(sr);
        sty[tid] = hw * fabsf(sr) + hh * fabsf(cr);
        slab[tid] = glab[gi];
        if (blockIdx.x == 0) { g_maxM[gi] = 0.0f; g_maxIou[gi] = 0.0f; }
    }
    if (tid == 0) s_nact = 0;

    // block anchor-point bbox (warp reduce then cross-warp)
    const float2 apt = *(const float2*)(ap + 2 * lc);
    const float ax = apt.x, ay = apt.y;
    {
        float x0 = ax, x1 = ax, y0 = ay, y1 = ay;
        #pragma unroll
        for (int o = 16; o > 0; o >>= 1) {
            x0 = fminf(x0, __shfl_xor_sync(0xffffffffu, x0, o));
            x1 = fmaxf(x1, __shfl_xor_sync(0xffffffffu, x1, o));
            y0 = fminf(y0, __shfl_xor_sync(0xffffffffu, y0, o));
            y1 = fmaxf(y1, __shfl_xor_sync(0xffffffffu, y1, o));
        }
        if (lane == 0) { s_wx0[wid] = x0; s_wx1[wid] = x1; s_wy0[wid] = y0; s_wy1[wid] = y1; }
    }
    __syncthreads();
    if (tid == 0) {
        float x0 = s_wx0[0], x1 = s_wx1[0], y0 = s_wy0[0], y1 = s_wy1[0];
        #pragma unroll
        for (int w = 1; w < 8; w++) {
            x0 = fminf(x0, s_wx0[w]); x1 = fmaxf(x1, s_wx1[w]);
            y0 = fminf(y0, s_wy0[w]); y1 = fmaxf(y1, s_wy1[w]);
        }
        s_bb[0] = x0; s_bb[1] = x1; s_bb[2] = y0; s_bb[3] = y1;
    }
    __syncthreads();

    // active-gt compaction: TRUE AABB vs block anchor-point bbox
    if (tid < n) {
        if (scx[tid] + stx[tid] >= s_bb[0] && scx[tid] - stx[tid] <= s_bb[1] &&
            scy[tid] + sty[tid] >= s_bb[2] && scy[tid] - sty[tid] <= s_bb[3]) {
            int q = atomicAdd(&s_nact, 1);
            s_act[q] = tid;
        }
    }
    __syncthreads();
    const int nact = s_nact;

    // anchor pred box (from staged smem)
    float cxp = s_prb[tid*5+0], cyp = s_prb[tid*5+1], wp = s_prb[tid*5+2],
          hp  = s_prb[tid*5+3], rp  = s_prb[tid*5+4];
    if (!valid) { cxp = 0; cyp = 0; wp = 0; hp = 0; rp = 0; }
    float mnx, mxx, mny, mxy;
    rbox_minmax(cxp, cyp, wp, hp, rp, mnx, mxx, mny, mxy);
    const float area = wp * hp;

    for (int t = 0; t < nact; t++) {
        int g = s_act[t];
        float dxp = ax - scx[g];
        float dyp = ay - scy[g];
        float xl =  dxp * scr[g] + dyp * ssr[g];
        float yl = -dxp * ssr[g] + dyp * scr[g];
        bool ing = valid && (fabsf(xl) <= shw[g]) && (fabsf(yl) <= shh[g]);

        unsigned mask = __ballot_sync(0xffffffffu, ing);
        if (mask) {
            int leader = __ffs(mask) - 1;
            int basep = 0;
            if (lane == leader) basep = atomicAdd(&g_ccnt[row0 + g], __popc(mask));
            basep = __shfl_sync(0xffffffffu, basep, leader);
            if (ing) {
                float iw = fminf(mxx, smxx[g]) - fmaxf(mnx, smnx[g]);
                float ih = fminf(mxy, smxy[g]) - fmaxf(mny, smny[g]);
                iw = fmaxf(iw, 0.0f);
                ih = fmaxf(ih, 0.0f);
                float inter = iw * ih;
                float den = area + sarea[g] - inter + 1e-9f;
                float iou = inter / den;
                iou = fminf(fmaxf(iou, 0.0f), 1.0f);
                float sc = __ldg(&ps[i * C + slab[g]]);
                float i2 = iou * iou;
                float met = sc * (i2 * i2 * i2);
                int p = basep + __popc(mask & lmlt);
                if (p < CAP) {
                    float4 e;
                    e.x = met; e.y = iou; e.z = __int_as_float(l); e.w = 0.0f;
                    g_cand[(size_t)(row0 + g) * CAP + p] = e;
                }
            }
        }
    }
    if (valid) {
        g_cnt[i] = 0;
        g_pk[i]  = ~0ULL;
    }
}

// ---------------- kernel C2: warp-per-row exact top-13 ----------------------
__global__ void kC2(const float* __restrict__ pad, int L, int n)
{
    __shared__ float sv[CAP];
    __shared__ int   si[CAP];
    __shared__ int   s_pos[16];
    __shared__ int   s_zp[16];
    __shared__ int   s_pcnt, s_need;

    int row  = blockIdx.x;                 // b*n + g
    int lane = threadIdx.x;                // 0..31
    int b = row / n;
    int g = row - b * n;
    bool padf = (pad[row] != 0.0f);

    int cnt = g_ccnt[row];
    if (cnt > CAP) cnt = CAP;
    size_t base  = (size_t)row * CAP;
    size_t abase = (size_t)b * L;
    unsigned long long gkey = (unsigned long long)g << 32;

    int npos = 0;
    for (int j = lane; j < cnt; j += 32) {
        float4 e = g_cand[base + j];
        sv[j] = e.x;
        si[j] = __float_as_int(e.z);
        if (e.x > 0.0f) npos++;
    }
    __syncwarp();
    #pragma unroll
    for (int o = 16; o > 0; o >>= 1) npos += __shfl_xor_sync(0xffffffffu, npos, o);

    if (npos >= TOPK) {
        for (int k = 0; k < TOPK; k++) {
            float bv = -1.0f; int bi = 0x7fffffff; int bslot = 0;
            for (int j = lane; j < cnt; j += 32) {
                float v = sv[j]; int ix = si[j];
                if (v > bv || (v == bv && ix < bi)) { bv = v; bi = ix; bslot = j; }
            }
            #pragma unroll
            for (int o = 16; o > 0; o >>= 1) {
                float ov = __shfl_xor_sync(0xffffffffu, bv, o);
                int   oi = __shfl_xor_sync(0xffffffffu, bi, o);
                int   os = __shfl_xor_sync(0xffffffffu, bslot, o);
                if (ov > bv || (ov == bv && oi < bi)) { bv = ov; bi = oi; bslot = os; }
            }
            if (lane == 0) {
                sv[bslot] = -1.0f;   // invalidate pick
                if (padf) {
                    atomicAdd(&g_cnt[abase + bi], 1);
                    atomicMin(&g_pk[abase + bi], gkey | (unsigned)bslot);
                }
            }
            __syncwarp();
        }
    } else {
        // all positives are picks; fill with lowest-index zero-valued anchors.
        if (lane == 0) s_pcnt = 0;
        __syncwarp();
        for (int j = lane; j < cnt; j += 32) {
            if (sv[j] > 0.0f) {
                int q = atomicAdd(&s_pcnt, 1);
                if (q < 16) s_pos[q] = si[j];
                if (padf) {
                    atomicAdd(&g_cnt[abase + si[j]], 1);
                    atomicMin(&g_pk[abase + si[j]], gkey | (unsigned)j);
                }
            }
        }
        __syncwarp();
        if (lane == 0) {
            int need = TOPK - npos;
            int nz = 0, idx = 0;
            while (nz < need && idx < L) {
                bool isp = false;
                for (int q = 0; q < npos && q < 16; q++)
                    if (s_pos[q] == idx) { isp = true; break; }
                if (!isp) s_zp[nz++] = idx;
                idx++;
            }
            s_need = nz;
        }
        __syncwarp();
        int need = s_need;
        // zero-metric candidates (in-gt) that coincide with fill picks count
        for (int j = lane; j < cnt; j += 32) {
            if (!(sv[j] > 0.0f)) {
                int ix = si[j];
                for (int q = 0; q < need; q++) {
                    if (s_zp[q] == ix) {
                        if (padf) {
                            atomicAdd(&g_cnt[abase + ix], 1);
                            atomicMin(&g_pk[abase + ix], gkey | (unsigned)j);
                        }
                        break;
                    }
                }
            }
        }
    }
    __syncwarp();
    if (lane == 0) g_ccnt[row] = 0;   // reset for next call (determinism)
}

// ---------------- kernel D: per-anchor assignment ---------------------------
__global__ void __launch_bounds__(NTD)
kD(const float* __restrict__ ps, const float* __restrict__ prb,
   const float* __restrict__ gtb, const int* __restrict__ glab,
   const int* __restrict__ gcrowd, const int* __restrict__ bgp,
   float* __restrict__ out, int B, int L, int C, int n)
{
    __shared__ float smnx[MAX_N], smxx[MAX_N], smny[MAX_N], smxy[MAX_N], sarea[MAX_N];
    __shared__ int   slab[MAX_N], scrowd[MAX_N];
    __shared__ float s_prb[NTD * 5];

    int b = blockIdx.y;
    int tid = threadIdx.x;
    int l0 = blockIdx.x * NTD;
    int l = l0 + tid;
    int row0 = b * n;

    {
        int nElem = min(NTD, L - l0) * 5;
        if (nElem > 0) {
            const float* src = prb + ((size_t)b * L + l0) * 5;
            for (int j = tid; j < nElem; j += NTD) s_prb[j] = src[j];
        }
    }
    if (tid < n) {
        int gi = row0 + tid;
        float cx = gtb[gi*5+0], cy = gtb[gi*5+1], w = gtb[gi*5+2], h = gtb[gi*5+3], r = gtb[gi*5+4];
        float mnx, mxx, mny, mxy;
        rbox_minmax(cx, cy, w, h, r, mnx, mxx, mny, mxy);
        smnx[tid] = mnx; smxx[tid] = mxx; smny[tid] = mny; smxy[tid] = mxy;
        sarea[tid] = w * h;
        slab[tid] = glab[gi];
        scrowd[tid] = gcrowd[gi];
    }
    __syncthreads();
    if (l >= L) return;

    size_t BL = (size_t)B * L;
    size_t i = (size_t)b * L + l;

    int cnt = g_cnt[i];
    unsigned long long pk = g_pk[i];
    int gf = 0; bool pos = false;
    float pm = 0.0f, piou = 0.0f;

    if (cnt == 1) {
        gf = (int)(pk >> 32);
        int slot = (int)(pk & 0xffffffffu);
        float4 e = g_cand[(size_t)(row0 + gf) * CAP + slot];
        pm = e.x; piou = e.y;
        pos = true;
    } else if (cnt > 1) {
        // argmax-iou over all gts (first-index tie-break), division-free
        float cx = s_prb[tid*5+0], cy = s_prb[tid*5+1], w = s_prb[tid*5+2],
              h  = s_prb[tid*5+3], r  = s_prb[tid*5+4];
        float mnx, mxx, mny, mxy;
        rbox_minmax(cx, cy, w, h, r, mnx, mxx, mny, mxy);
        float area = w * h;
        float numb = -1.0f, denb = 1.0f;
        for (int g = 0; g < n; g++) {
            float iw = fminf(mxx, smxx[g]) - fmaxf(mnx, smnx[g]);
            float ih = fminf(mxy, smxy[g]) - fmaxf(mny, smny[g]);
            iw = fmaxf(iw, 0.0f);
            ih = fmaxf(ih, 0.0f);
            float inter = iw * ih;
            float den = area + sarea[g] - inter + 1e-9f;
            if (inter * denb > numb * den) { numb = inter; denb = den; gf = g; }
        }
        piou = numb / denb;
        piou = fminf(fmaxf(piou, 0.0f), 1.0f);
        float sc = __ldg(&ps[i * C + slab[gf]]);
        float i2 = piou * piou;
        pm = sc * (i2 * i2 * i2);
        pos = true;
    }

    g_gfin[i] = pos ? gf : -1;
    g_posM[i] = pm;
    if (pos) {
        atomicMax((int*)&g_maxM[row0 + gf],   __float_as_int(pm));
        atomicMax((int*)&g_maxIou[row0 + gf], __float_as_int(piou));
    }

    int bg = bgp ? bgp[0] : C;
    out[i] = pos ? (float)slab[gf] : (float)bg;               // labels
    const float* gb = gtb + (size_t)(row0 + gf) * 5;
    #pragma unroll
    for (int j = 0; j < 5; j++) out[BL + i*5 + j] = gb[j];    // rboxes
    out[BL * (size_t)(6 + C) + i] = (float)gf;                // gt index
    out[BL * (size_t)(7 + C) + i] = (float)scrowd[gf];        // crowd
}

// ---------------- kernel E3: scores — thread per anchor, smem staged --------
// C == MAX_C specialization (compile-time divisions); block = NT anchors.
__global__ void __launch_bounds__(NT)
kE3(const int* __restrict__ glab, const int* __restrict__ gcrowd,
    const int* __restrict__ bgp, float* __restrict__ out,
    int B, int L, int n)
{
    __shared__ float s_row[NT * MAX_C];

    size_t BL = (size_t)B * L;
    size_t i0 = (size_t)blockIdx.x * NT;
    size_t i = i0 + threadIdx.x;
    int tid = threadIdx.x;

    float pa = 0.0f;
    int col = -1;
    if (i < BL) {
        int gf = g_gfin[i];
        if (gf >= 0) {
            int b = (int)(i / L);
            int gi = b * n + gf;
            int lab = glab[gi];
            int bg = bgp ? bgp[0] : MAX_C;
            if (gcrowd[gi] == 0 && lab != bg) {
                col = (lab > bg) ? (lab - 1) : lab;
                pa = g_posM[i] / (g_maxM[gi] + 1e-9f) * g_maxIou[gi];
            }
        }
    }
    #pragma unroll
    for (int c = 0; c < MAX_C; c++) s_row[tid * MAX_C + c] = (c == col) ? pa : 0.0f;
    __syncthreads();

    // coalesced copy to gmem
    size_t nAnch = (i0 + NT <= BL) ? NT : (BL > i0 ? BL - i0 : 0);
    int tot = (int)nAnch * MAX_C;
    float* dst = out + BL * 6 + i0 * MAX_C;
    for (int j = tid; j < tot; j += NT) dst[j] = s_row[j];
}

// generic fallback (C != MAX_C)
__global__ void kE2g(const int* __restrict__ glab, const int* __restrict__ gcrowd,
                     const int* __restrict__ bgp, float* __restrict__ out,
                     int B, int L, int C, int n)
{
    size_t BL = (size_t)B * L;
    size_t t = (size_t)blockIdx.x * blockDim.x + threadIdx.x;
    if (t >= BL * (size_t)C) return;
    size_t i = t / (size_t)C;
    int c = (int)(t - i * (size_t)C);
    int b = (int)(i / L);

    int gf = g_gfin[i];
    float val = 0.0f;
    if (gf >= 0) {
        int gi = b * n + gf;
        int lab = glab[gi];
        int bg = bgp ? bgp[0] : C;
        if (gcrowd[gi] == 0 && lab != bg) {
            int col = (lab > bg) ? (lab - 1) : lab;
            if (col == c) val = g_posM[i] / (g_maxM[gi] + 1e-9f) * g_maxIou[gi];
        }
    }
    out[BL * 6 + t] = val;
}

// ---------------- launch -----------------------------------------------------
extern "C" void kernel_launch(void* const* d_in, const int* in_sizes, int n_in,
                              void* d_out, int out_size)
{
    const float* pred_scores = (const float*)d_in[0];
    const float* pred_rboxes = (const float*)d_in[1];
    const float* anchor      = (const float*)d_in[2];

    int L = in_sizes[2] / 2;
    int B = in_sizes[1] / (5 * L);
    int C = in_sizes[0] / (B * L);
    int n = in_sizes[3] / B;
    int BN = B * n;
    size_t BL = (size_t)B * L;

    const int*   glab = (const int*)d_in[3];       // int32 (JAX x64 disabled)
    const float* gtb  = (const float*)d_in[4];

    int idx = 5;
    if (idx < n_in && in_sizes[idx] == 3 * BN) idx++;   // skip gt_poses
    const int*   gcrowd = (const int*)d_in[idx];  idx++;
    const float* pad    = (const float*)d_in[idx]; idx++;
    const int*   bgp    = (idx < n_in && in_sizes[idx] == 1) ? (const int*)d_in[idx] : nullptr;

    dim3 gB((L + NT - 1) / NT, B);
    kB<<<gB, NT>>>(pred_scores, pred_rboxes, anchor, gtb, glab, B, L, C, n);

    kC2<<<BN, 32>>>(pad, L, n);

    dim3 gD((L + NTD - 1) / NTD, B);
    kD<<<gD, NTD>>>(pred_scores, pred_rboxes, gtb, glab, gcrowd, bgp, (float*)d_out, B, L, C, n);

    if (C == MAX_C) {
        int blocks = (int)((BL + NT - 1) / NT);
        kE3<<<blocks, NT>>>(glab, gcrowd, bgp, (float*)d_out, B, L, n);
    } else {
        size_t totE = BL * (size_t)C;
        kE2g<<<(int)((totE + NT - 1) / NT), NT>>>(glab, gcrowd, bgp, (float*)d_out, B, L, C, n);
    }
}